// round 13
// baseline (speedup 1.0000x reference)
#include <cuda_runtime.h>
#include <cstdint>
#include <math.h>

#define BANDS 32
#define CHA 128
#define NPIX 4096
#define TOTN 16777216u
#define KSP 4
#define KC2 1024
#define ITE 10
#define SST 36

// ---------------- device scratch ----------------
__device__ float d_L[16777216];
__device__ float d_Gp[KSP * BANDS * CHA * CHA];   // P = hi*hi^T + hi*lo^T partials
__device__ float d_Gs[KSP * BANDS * CHA * CHA];   // S = hi*lo^T partials
__device__ float d_G[BANDS * CHA * CHA];
__device__ float d_U[BANDS * CHA * 3];
__device__ float d_Yw[BANDS * CHA * 16];
__device__ float d_red[1024];
__device__ float d_loss[512 * 2];
__device__ float d_rho0;

__device__ __forceinline__ float hashf(uint32_t h) {
    h ^= h >> 16; h *= 0x7feb352du; h ^= h >> 15; h *= 0x846ca68bu; h ^= h >> 16;
    return (float)(h & 0xffffffu) * (1.0f / 16777216.0f) - 0.5f;
}

// ---------------- L = x ----------------
__global__ void k_copy(const float* __restrict__ x) {
    unsigned i = blockIdx.x * blockDim.x + threadIdx.x;
    unsigned st = gridDim.x * blockDim.x;
    const float4* x4 = (const float4*)x;
    float4* L4 = (float4*)d_L;
    for (unsigned j = i; j < TOTN / 4; j += st) L4[j] = x4[j];
}

// ---------------- rho0 ----------------
__global__ void k_wsum(const float* __restrict__ W) {
    __shared__ float sr[256];
    float s = 0.f;
    unsigned st = gridDim.x * blockDim.x;
    for (unsigned i = blockIdx.x * blockDim.x + threadIdx.x; i < TOTN; i += st) s += W[i];
    sr[threadIdx.x] = s; __syncthreads();
    for (int o = 128; o >= 1; o >>= 1) { if ((int)threadIdx.x < o) sr[threadIdx.x] += sr[threadIdx.x + o]; __syncthreads(); }
    if (threadIdx.x == 0) d_red[blockIdx.x] = sr[0];
}
__global__ void k_rho() {
    __shared__ double sd[256];
    int t = threadIdx.x;
    double s = 0.0;
    for (int j = t; j < 1024; j += 256) s += (double)d_red[j];
    sd[t] = s; __syncthreads();
    for (int o = 128; o >= 1; o >>= 1) { if (t < o) sd[t] += sd[t + o]; __syncthreads(); }
    if (t == 0) d_rho0 = (float)(0.5 * sd[0] / (double)TOTN);
}

// ---------------- mma.sync tf32 helpers ----------------
__device__ __forceinline__ void mma8(float* c, const uint32_t* a, uint32_t b0, uint32_t b1) {
    asm volatile(
        "mma.sync.aligned.m16n8k8.row.col.f32.tf32.tf32.f32 "
        "{%0,%1,%2,%3}, {%4,%5,%6,%7}, {%8,%9}, {%0,%1,%2,%3};"
        : "+f"(c[0]), "+f"(c[1]), "+f"(c[2]), "+f"(c[3])
        : "r"(a[0]), "r"(a[1]), "r"(a[2]), "r"(a[3]), "r"(b0), "r"(b1));
}
__device__ __forceinline__ uint32_t cvt_tf32(float x) {
    uint32_t r;
    asm("cvt.rna.tf32.f32 %0, %1;" : "=r"(r) : "f"(x));
    return r;
}

// ---------------- tensor syrk: P = hh+hl, S = hl (+ folded loss reduction of prev iter) ----------------
__global__ __launch_bounds__(512) void k_syrk_mma(float* __restrict__ out, int prev_iter) {
    __shared__ uint32_t Hs[128 * SST];
    __shared__ uint32_t Lo[128 * SST];
    int tid = threadIdx.x, lane = tid & 31, w = tid >> 5;
    int gid = lane >> 2, tig = lane & 3;
    int ks = blockIdx.x, b = blockIdx.y;

    // folded loss reduction for previous iteration (one warp of CTA (0,0))
    if (prev_iter >= 0 && ks == 0 && b == 0 && w == 0) {
        double s0 = 0.0, s1 = 0.0;
        for (int j = lane; j < 128; j += 32) {
            s0 += (double)d_loss[j * 2];
            s1 += (double)d_loss[j * 2 + 1];
        }
#pragma unroll
        for (int off = 16; off >= 1; off >>= 1) {
            s0 += __shfl_down_sync(0xffffffffu, s0, off);
            s1 += __shfl_down_sync(0xffffffffu, s1, off);
        }
        if (lane == 0) {
            out[TOTN + prev_iter] = (float)(s1 / (double)TOTN);        // loss_F
            out[TOTN + 10 + prev_iter] = (float)(s0 / (double)TOTN);   // loss
        }
    }

    const float* Lb = d_L + (size_t)b * CHA * NPIX + (size_t)ks * KC2;
    int wr = w >> 2, wc = w & 3;   // warp tile: rows 32*wr, cols 32*wc

    float accH[8][4], accS[8][4];
#pragma unroll
    for (int i = 0; i < 8; i++)
#pragma unroll
        for (int j = 0; j < 4; j++) { accH[i][j] = 0.f; accS[i][j] = 0.f; }

    int f0 = tid * 2;
    float4 pf[2];
#pragma unroll
    for (int i = 0; i < 2; i++) {
        int f = f0 + i, row = f >> 3, c4 = f & 7;
        pf[i] = *(const float4*)&Lb[(size_t)row * NPIX + c4 * 4];
    }

    for (int s = 0; s < 32; s++) {
#pragma unroll
        for (int i = 0; i < 2; i++) {
            int f = f0 + i, row = f >> 3, c4 = f & 7;
            int base = row * SST + c4 * 4;
            float v[4] = {pf[i].x, pf[i].y, pf[i].z, pf[i].w};
#pragma unroll
            for (int j = 0; j < 4; j++) {
                uint32_t h = cvt_tf32(v[j]);
                Hs[base + j] = h;
                Lo[base + j] = cvt_tf32(v[j] - __uint_as_float(h));
            }
        }
        __syncthreads();
        if (s < 31) {
#pragma unroll
            for (int i = 0; i < 2; i++) {
                int f = f0 + i, row = f >> 3, c4 = f & 7;
                pf[i] = *(const float4*)&Lb[(size_t)row * NPIX + (s + 1) * 32 + c4 * 4];
            }
        }
#pragma unroll
        for (int kst = 0; kst < 4; kst++) {
            int k0 = kst * 8;
            uint32_t ah[2][4];
#pragma unroll
            for (int h = 0; h < 2; h++) {
                int m = wr * 32 + h * 16;
                ah[h][0] = Hs[(m + gid) * SST + k0 + tig];
                ah[h][1] = Hs[(m + gid + 8) * SST + k0 + tig];
                ah[h][2] = Hs[(m + gid) * SST + k0 + tig + 4];
                ah[h][3] = Hs[(m + gid + 8) * SST + k0 + tig + 4];
            }
#pragma unroll
            for (int nt = 0; nt < 4; nt++) {
                int n = wc * 32 + nt * 8 + gid;
                uint32_t bh0 = Hs[n * SST + k0 + tig];
                uint32_t bh1 = Hs[n * SST + k0 + tig + 4];
                uint32_t bl0 = Lo[n * SST + k0 + tig];
                uint32_t bl1 = Lo[n * SST + k0 + tig + 4];
#pragma unroll
                for (int h = 0; h < 2; h++) {
                    mma8(accH[h * 4 + nt], ah[h], bh0, bh1);
                    mma8(accS[h * 4 + nt], ah[h], bl0, bl1);
                }
            }
        }
        __syncthreads();
    }

    float* Gp = d_Gp + ((size_t)ks * BANDS + b) * CHA * CHA;
    float* Gs = d_Gs + ((size_t)ks * BANDS + b) * CHA * CHA;
#pragma unroll
    for (int h = 0; h < 2; h++) {
        int m = wr * 32 + h * 16;
#pragma unroll
        for (int nt = 0; nt < 4; nt++) {
            int n = wc * 32 + nt * 8 + 2 * tig;
            int t = h * 4 + nt;
            *(float2*)&Gp[(size_t)(m + gid) * 128 + n] =
                make_float2(accH[t][0] + accS[t][0], accH[t][1] + accS[t][1]);
            *(float2*)&Gp[(size_t)(m + gid + 8) * 128 + n] =
                make_float2(accH[t][2] + accS[t][2], accH[t][3] + accS[t][3]);
            *(float2*)&Gs[(size_t)(m + gid) * 128 + n] = make_float2(accS[t][0], accS[t][1]);
            *(float2*)&Gs[(size_t)(m + gid + 8) * 128 + n] = make_float2(accS[t][2], accS[t][3]);
        }
    }
}

// ---------------- G = sum_ks (P + S^T)  (round-9 version) ----------------
__global__ void k_gsum() {
    unsigned idx = blockIdx.x * 2048u + threadIdx.x;
    for (unsigned e = idx; e < idx + 2048u; e += 256u) {
        unsigned bb = e >> 14, i = (e >> 7) & 127u, j = e & 127u;
        float s = 0.f;
#pragma unroll
        for (int ks = 0; ks < KSP; ks++) {
            size_t base = ((size_t)ks * BANDS + bb) * CHA * CHA;
            s += d_Gp[base + i * 128 + j];
            s += d_Gs[base + j * 128 + i];
        }
        d_G[e] = s;
    }
}

// ---------------- eig helpers ----------------
#define AS 132
#define YS 20
#define CS 18

// 512-thread matY: dst(128x16) = A * Ys
__device__ void matY(float* dst, const float* A, int st, const float* Ys, int tid) {
    int i0 = (tid & 31) * 4, j = tid >> 5;   // j in 0..15
    float a0 = 0.f, a1 = 0.f, a2 = 0.f, a3 = 0.f;
#pragma unroll 4
    for (int k = 0; k < 128; k++) {
        float4 a = *(const float4*)&A[k * st + i0];
        float y = Ys[k * YS + j];
        a0 += a.x * y; a1 += a.y * y; a2 += a.z * y; a3 += a.w * y;
    }
    dst[(i0 + 0) * YS + j] = a0;
    dst[(i0 + 1) * YS + j] = a1;
    dst[(i0 + 2) * YS + j] = a2;
    dst[(i0 + 3) * YS + j] = a3;
    __syncthreads();
}

__device__ void qrP(float* Yb, float* red, int tid, int passes) {
    for (int j = 0; j < 16; j++) {
        for (int pass = 0; pass < passes; pass++) {
            if (j > 0) {
                if (tid < 256) {
                    int i = tid >> 4, kc = tid & 15;
                    float pp = 0.f;
                    if (i < j) {
#pragma unroll
                        for (int kk = 0; kk < 8; kk++) {
                            int k = kc * 8 + kk;
                            pp += Yb[k * YS + i] * Yb[k * YS + j];
                        }
                    }
                    red[i * 16 + kc] = pp;
                }
                __syncthreads();
                if (tid < 16) {
                    float s = 0.f;
#pragma unroll
                    for (int q = 0; q < 16; q++) s += red[tid * 16 + q];
                    red[256 + tid] = s;
                }
                __syncthreads();
                if (tid < 128) {
                    float v = Yb[tid * YS + j];
                    for (int i2 = 0; i2 < j; i2++) v -= red[256 + i2] * Yb[tid * YS + i2];
                    Yb[tid * YS + j] = v;
                }
                __syncthreads();
            }
        }
        float v = (tid < 128) ? Yb[tid * YS + j] : 0.f;
        if (tid < 256) red[tid] = v * v;
        __syncthreads();
        if (tid < 64) red[tid] += red[tid + 64] + red[tid + 128] + red[tid + 192];
        __syncthreads();
        if (tid < 32) {
            float s = red[tid] + red[tid + 32];
#pragma unroll
            for (int off = 16; off >= 1; off >>= 1) s += __shfl_down_sync(0xffffffffu, s, off);
            if (tid == 0) red[0] = s;
        }
        __syncthreads();
        float inv = rsqrtf(fmaxf(red[0], 1e-36f));
        if (tid < 128) Yb[tid * YS + j] = v * inv;
        __syncthreads();
    }
}

__device__ void jacobi16(float* Bm, float* Vm, int* pr, float* cs, int tid) {
    if (tid < 16)
        for (int q = 0; q < 16; q++) Vm[tid * CS + q] = (tid == q) ? 1.f : 0.f;
    __syncthreads();
    for (int sweep = 0; sweep < 5; sweep++) {
        for (int r = 0; r < 15; r++) {
            if (tid < 8) {
                int m = tid;
                int p = (m == 0) ? 0 : 1 + ((m - 1 + r) % 15);
                int q = 1 + ((14 - m + r) % 15);
                if (p > q) { int tmp = p; p = q; q = tmp; }
                float app = Bm[p * CS + p], aqq = Bm[q * CS + q], apq = Bm[p * CS + q];
                float c = 1.f, s = 0.f;
                if (fabsf(apq) > 1e-30f) {
                    float tau = (aqq - app) / (2.f * apq);
                    float tt = ((tau >= 0.f) ? 1.f : -1.f) / (fabsf(tau) + sqrtf(1.f + tau * tau));
                    c = rsqrtf(1.f + tt * tt);
                    s = tt * c;
                }
                pr[m * 2] = p; pr[m * 2 + 1] = q;
                cs[m * 2] = c; cs[m * 2 + 1] = s;
            }
            __syncthreads();
            if (tid < 128) {
                int m = tid >> 4, k = tid & 15;
                int p = pr[m * 2], q = pr[m * 2 + 1];
                float c = cs[m * 2], s = cs[m * 2 + 1];
                float bp = Bm[p * CS + k], bq = Bm[q * CS + k];
                Bm[p * CS + k] = c * bp - s * bq;
                Bm[q * CS + k] = s * bp + c * bq;
            }
            __syncthreads();
            if (tid < 128) {
                int m = tid >> 4, k = tid & 15;
                int p = pr[m * 2], q = pr[m * 2 + 1];
                float c = cs[m * 2], s = cs[m * 2 + 1];
                float bp = Bm[k * CS + p], bq = Bm[k * CS + q];
                Bm[k * CS + p] = c * bp - s * bq;
                Bm[k * CS + q] = s * bp + c * bq;
                float vp = Vm[k * CS + p], vq = Vm[k * CS + q];
                Vm[k * CS + p] = c * vp - s * vq;
                Vm[k * CS + q] = s * vp + c * vq;
            }
            __syncthreads();
        }
    }
}

// ---------------- per-band: MMA squaring chain (G^32) + subspace + RR, 512 threads ----------------
__global__ __launch_bounds__(512) void k_eig(int iter) {
    extern __shared__ float sm[];
    float* A   = sm;                        // 128*AS — squaring buffer 0 / RR G tile
    float* Y   = A + 128 * AS;
    float* Y2  = Y + 128 * YS;
    float* C   = Y2 + 128 * YS;
    float* V   = C + 16 * CS;
    float* red = V + 16 * CS;
    float* cs  = red + 320;
    int*   pr  = (int*)(cs + 32);
    uint32_t* B1 = (uint32_t*)(pr + 32);    // 128*AS — squaring buffer 1
    uint32_t* B0 = (uint32_t*)A;
    int tid = threadIdx.x, b = blockIdx.x;
    int lane = tid & 31, w = tid >> 5;
    int gid = lane >> 2, tig = lane & 3;
    int wr = w >> 1, wc = w & 1;            // 16 warps: tile 16 rows x 64 cols

    const float* Gb = d_G + (size_t)b * CHA * CHA;
    for (int e = tid; e < CHA * CHA; e += 512)
        B0[(e >> 7) * AS + (e & 127)] = cvt_tf32(Gb[e]);
    __syncthreads();

    uint32_t* src = B0;
    uint32_t* dst = B1;
    for (int sq = 0; sq < 5; sq++) {
        float acc[8][4];
#pragma unroll
        for (int i = 0; i < 8; i++)
#pragma unroll
            for (int j = 0; j < 4; j++) acc[i][j] = 0.f;
        int m = wr * 16;
#pragma unroll 2
        for (int kst = 0; kst < 16; kst++) {
            int k0 = kst * 8;
            uint32_t a[4];
            a[0] = src[(m + gid) * AS + k0 + tig];
            a[1] = src[(m + gid + 8) * AS + k0 + tig];
            a[2] = src[(m + gid) * AS + k0 + tig + 4];
            a[3] = src[(m + gid + 8) * AS + k0 + tig + 4];
#pragma unroll
            for (int nt = 0; nt < 8; nt++) {
                int n = wc * 64 + nt * 8 + gid;
                uint32_t b0 = src[n * AS + k0 + tig];
                uint32_t b1 = src[n * AS + k0 + tig + 4];
                mma8(acc[nt], a, b0, b1);
            }
        }
        float dm = 0.f;
#pragma unroll
        for (int nt = 0; nt < 8; nt++) {
            int R = m + gid, Ncol = wc * 64 + nt * 8 + 2 * tig;
            if (R == Ncol) dm = fmaxf(dm, fabsf(acc[nt][0]));
            if (R == Ncol + 1) dm = fmaxf(dm, fabsf(acc[nt][1]));
            if (R + 8 == Ncol) dm = fmaxf(dm, fabsf(acc[nt][2]));
            if (R + 8 == Ncol + 1) dm = fmaxf(dm, fabsf(acc[nt][3]));
        }
#pragma unroll
        for (int off = 16; off >= 1; off >>= 1) dm = fmaxf(dm, __shfl_xor_sync(0xffffffffu, dm, off));
        if (lane == 0) red[w] = dm;
        __syncthreads();
        float d = 1e-30f;
#pragma unroll
        for (int q = 0; q < 16; q++) d = fmaxf(d, red[q]);
        float inv = 1.0f / d;
#pragma unroll
        for (int nt = 0; nt < 8; nt++) {
            int R = m + gid, Ncol = wc * 64 + nt * 8 + 2 * tig;
            dst[R * AS + Ncol] = cvt_tf32(acc[nt][0] * inv);
            dst[R * AS + Ncol + 1] = cvt_tf32(acc[nt][1] * inv);
            dst[(R + 8) * AS + Ncol] = cvt_tf32(acc[nt][2] * inv);
            dst[(R + 8) * AS + Ncol + 1] = cvt_tf32(acc[nt][3] * inv);
        }
        __syncthreads();
        uint32_t* tmp = src; src = dst; dst = tmp;
    }
    const float* F = (const float*)src;   // == B1 after 5 swaps

    if (iter == 0) {
        for (int e = tid; e < 128 * 16; e += 512) {
            int k = e >> 4, j = e & 15;
            Y[k * YS + j] = hashf((uint32_t)((b * 131) * 2048 + e) * 2654435761u + 12345u);
        }
        __syncthreads();
        matY(Y2, F, AS, Y, tid);  qrP(Y2, red, tid, 1);
        matY(Y, F, AS, Y2, tid);  qrP(Y, red, tid, 1);
        matY(Y2, F, AS, Y, tid);  qrP(Y2, red, tid, 2);
    } else {
        const float* Yw = d_Yw + (size_t)b * 128 * 16;
        for (int e = tid; e < 128 * 16; e += 512) {
            int k = e >> 4, j = e & 15;
            Y[k * YS + j] = Yw[e];
        }
        __syncthreads();
        matY(Y2, F, AS, Y, tid);  qrP(Y2, red, tid, 2);
    }

    {
        float* Yw = d_Yw + (size_t)b * 128 * 16;
        for (int e = tid; e < 128 * 16; e += 512) {
            int k = e >> 4, j = e & 15;
            Yw[e] = Y2[k * YS + j];
        }
    }

    // Rayleigh-Ritz against exact fp32 G (reload into A; F lives in B1, untouched)
    for (int e = tid; e < CHA * CHA; e += 512)
        A[(e >> 7) * AS + (e & 127)] = Gb[e];
    __syncthreads();
    matY(Y, A, AS, Y2, tid);

    if (tid < 256) {
        int a = tid & 15, bb = tid >> 4;
        float s = 0.f;
        for (int k = 0; k < 128; k++) s += Y2[k * YS + a] * Y[k * YS + bb];
        C[a * CS + bb] = s;
    }
    __syncthreads();

    jacobi16(C, V, pr, cs, tid);

    if (tid == 0) {
        int sel[3] = {-1, -1, -1};
        for (int r = 0; r < 3; r++) {
            float best = -1e30f; int bi = 0;
            for (int j = 0; j < 16; j++) {
                bool used = (j == sel[0]) || (j == sel[1]) || (j == sel[2]);
                float ev = C[j * CS + j];
                if (!used && ev > best) { best = ev; bi = j; }
            }
            sel[r] = bi; pr[r] = bi;
        }
    }
    __syncthreads();

    if (tid < 128) {
        for (int r = 0; r < 3; r++) {
            int j = pr[r];
            float u = 0.f;
#pragma unroll
            for (int q = 0; q < 16; q++) u += Y2[tid * YS + q] * V[q * CS + j];
            d_U[(size_t)b * 384 + tid * 3 + r] = u;
        }
    }
}

// ---------------- fused UtL + update L + losses + final UV (float4, round-9 grid) ----------------
__global__ __launch_bounds__(256) void k_update(const float* __restrict__ x, const float* __restrict__ W,
                                                const float* __restrict__ xg, float* __restrict__ out,
                                                int iter, int wout) {
    __shared__ float sU[384];
    __shared__ float sr[256];
    int b = blockIdx.y, tid = threadIdx.x;
    int n = (blockIdx.x * 256 + tid) * 4;
    if (tid < 128) {
        sU[tid * 3]     = d_U[(size_t)b * 384 + tid * 3];
        sU[tid * 3 + 1] = d_U[(size_t)b * 384 + tid * 3 + 1];
        sU[tid * 3 + 2] = d_U[(size_t)b * 384 + tid * 3 + 2];
    }
    __syncthreads();

    const float* Lb = d_L + (size_t)b * CHA * NPIX;
    float4 t0 = {0,0,0,0}, t1 = {0,0,0,0}, t2 = {0,0,0,0};
#pragma unroll 4
    for (int c = 0; c < 128; c++) {
        float4 v = *(const float4*)&Lb[(size_t)c * NPIX + n];
        float u0 = sU[c * 3], u1 = sU[c * 3 + 1], u2 = sU[c * 3 + 2];
        t0.x += u0 * v.x; t0.y += u0 * v.y; t0.z += u0 * v.z; t0.w += u0 * v.w;
        t1.x += u1 * v.x; t1.y += u1 * v.y; t1.z += u1 * v.z; t1.w += u1 * v.w;
        t2.x += u2 * v.x; t2.y += u2 * v.y; t2.z += u2 * v.z; t2.w += u2 * v.w;
    }

    float rho = d_rho0 * powf(1.05f, (float)iter);
    float ls = 0.f, lf = 0.f;
    for (int c = 0; c < 128; c++) {
        size_t idx = ((size_t)b * 128 + c) * NPIX + n;
        float u0 = sU[c * 3], u1 = sU[c * 3 + 1], u2 = sU[c * 3 + 2];
        float4 xv = *(const float4*)&x[idx];
        float4 wv = *(const float4*)&W[idx];
        float4 gv = *(const float4*)&xg[idx];
        float4 uv;
        uv.x = u0 * t0.x + u1 * t1.x + u2 * t2.x;
        uv.y = u0 * t0.y + u1 * t1.y + u2 * t2.y;
        uv.z = u0 * t0.z + u1 * t1.z + u2 * t2.z;
        uv.w = u0 * t0.w + u1 * t1.w + u2 * t2.w;
        float4 Lnew;
        {
            float d0 = uv.x - gv.x, d1 = uv.y - gv.y, d2 = uv.z - gv.z, d3 = uv.w - gv.w;
            ls += d0*d0 + d1*d1 + d2*d2 + d3*d3;
            float e0 = uv.x - xv.x, e1 = uv.y - xv.y, e2 = uv.z - xv.z, e3 = uv.w - xv.w;
            lf += wv.x*e0*e0 + wv.y*e1*e1 + wv.z*e2*e2 + wv.w*e3*e3;
            float m0 = rho / (wv.x + rho), m1 = rho / (wv.y + rho);
            float m2 = rho / (wv.z + rho), m3 = rho / (wv.w + rho);
            Lnew.x = (1.f - m0) * xv.x + m0 * uv.x;
            Lnew.y = (1.f - m1) * xv.y + m1 * uv.y;
            Lnew.z = (1.f - m2) * xv.z + m2 * uv.z;
            Lnew.w = (1.f - m3) * xv.w + m3 * uv.w;
        }
        *(float4*)&d_L[idx] = Lnew;
        if (wout) *(float4*)&out[idx] = uv;
    }
    sr[tid] = ls; __syncthreads();
    for (int o = 128; o >= 1; o >>= 1) { if (tid < o) sr[tid] += sr[tid + o]; __syncthreads(); }
    if (tid == 0) d_loss[(blockIdx.y * 4 + blockIdx.x) * 2] = sr[0];
    __syncthreads();
    sr[tid] = lf; __syncthreads();
    for (int o = 128; o >= 1; o >>= 1) { if (tid < o) sr[tid] += sr[tid + o]; __syncthreads(); }
    if (tid == 0) d_loss[(blockIdx.y * 4 + blockIdx.x) * 2 + 1] = sr[0];
}

__global__ void k_lossred(float* out, int iter) {
    __shared__ double sd[512];
    int t = threadIdx.x;
    double s0 = 0.0, s1 = 0.0;
    for (int j = t; j < 128; j += 256) { s0 += (double)d_loss[j * 2]; s1 += (double)d_loss[j * 2 + 1]; }
    sd[t] = s0; sd[256 + t] = s1; __syncthreads();
    for (int o = 128; o >= 1; o >>= 1) {
        if (t < o) { sd[t] += sd[t + o]; sd[256 + t] += sd[256 + t + o]; }
        __syncthreads();
    }
    if (t == 0) {
        out[TOTN + iter] = (float)(sd[256] / (double)TOTN);
        out[TOTN + 10 + iter] = (float)(sd[0] / (double)TOTN);
    }
}

// ---------------- launch ----------------
extern "C" void kernel_launch(void* const* d_in, const int* in_sizes, int n_in,
                              void* d_out, int out_size) {
    const float* x = (const float*)d_in[0];
    const float* W = (const float*)d_in[1];
    const float* xg = (const float*)d_in[2];
    float* out = (float*)d_out;

    size_t eigsm = (size_t)(2 * 128 * AS + 2 * 128 * YS + 2 * 16 * CS + 320 + 32 + 32) * 4;
    cudaFuncSetAttribute(k_eig, cudaFuncAttributeMaxDynamicSharedMemorySize, 164 * 1024);

    k_copy<<<1024, 256>>>(x);
    k_wsum<<<1024, 256>>>(W);
    k_rho<<<1, 256>>>();

    for (int i = 0; i < ITE; i++) {
        k_syrk_mma<<<dim3(KSP, BANDS), 512>>>(out, i - 1);
        k_gsum<<<256, 256>>>();
        k_eig<<<BANDS, 512, eigsm>>>(i);
        k_update<<<dim3(4, BANDS), 256>>>(x, W, xg, out, i, (i == ITE - 1) ? 1 : 0);
    }
    k_lossred<<<1, 256>>>(out, ITE - 1);
}

// round 15
// speedup vs baseline: 1.0490x; 1.0490x over previous
#include <cuda_runtime.h>
#include <cstdint>
#include <math.h>

#define BANDS 32
#define CHA 128
#define NPIX 4096
#define TOTN 16777216u
#define KSP 4
#define KC2 1024
#define ITE 10
#define SST 36
#define BUFW (2 * 128 * SST)   // one stage buffer: Hs + Lo (uint32 words)

// ---------------- device scratch ----------------
__device__ float d_L[16777216];
__device__ float d_Gp[KSP * BANDS * CHA * CHA];
__device__ float d_Gs[KSP * BANDS * CHA * CHA];
__device__ float d_G[BANDS * CHA * CHA];
__device__ float d_U[BANDS * CHA * 3];
__device__ float d_Yw[BANDS * CHA * 16];
__device__ float d_red[1024];
__device__ float d_loss[512 * 2];
__device__ float d_rho0;

__device__ __forceinline__ float hashf(uint32_t h) {
    h ^= h >> 16; h *= 0x7feb352du; h ^= h >> 15; h *= 0x846ca68bu; h ^= h >> 16;
    return (float)(h & 0xffffffu) * (1.0f / 16777216.0f) - 0.5f;
}

// ---------------- L = x ----------------
__global__ void k_copy(const float* __restrict__ x) {
    unsigned i = blockIdx.x * blockDim.x + threadIdx.x;
    unsigned st = gridDim.x * blockDim.x;
    const float4* x4 = (const float4*)x;
    float4* L4 = (float4*)d_L;
    for (unsigned j = i; j < TOTN / 4; j += st) L4[j] = x4[j];
}

// ---------------- rho0 ----------------
__global__ void k_wsum(const float* __restrict__ W) {
    __shared__ float sr[256];
    float s = 0.f;
    unsigned st = gridDim.x * blockDim.x;
    for (unsigned i = blockIdx.x * blockDim.x + threadIdx.x; i < TOTN; i += st) s += W[i];
    sr[threadIdx.x] = s; __syncthreads();
    for (int o = 128; o >= 1; o >>= 1) { if ((int)threadIdx.x < o) sr[threadIdx.x] += sr[threadIdx.x + o]; __syncthreads(); }
    if (threadIdx.x == 0) d_red[blockIdx.x] = sr[0];
}
__global__ void k_rho() {
    __shared__ double sd[256];
    int t = threadIdx.x;
    double s = 0.0;
    for (int j = t; j < 1024; j += 256) s += (double)d_red[j];
    sd[t] = s; __syncthreads();
    for (int o = 128; o >= 1; o >>= 1) { if (t < o) sd[t] += sd[t + o]; __syncthreads(); }
    if (t == 0) d_rho0 = (float)(0.5 * sd[0] / (double)TOTN);
}

// ---------------- mma.sync tf32 helpers ----------------
__device__ __forceinline__ void mma8(float* c, const uint32_t* a, uint32_t b0, uint32_t b1) {
    asm volatile(
        "mma.sync.aligned.m16n8k8.row.col.f32.tf32.tf32.f32 "
        "{%0,%1,%2,%3}, {%4,%5,%6,%7}, {%8,%9}, {%0,%1,%2,%3};"
        : "+f"(c[0]), "+f"(c[1]), "+f"(c[2]), "+f"(c[3])
        : "r"(a[0]), "r"(a[1]), "r"(a[2]), "r"(a[3]), "r"(b0), "r"(b1));
}
__device__ __forceinline__ uint32_t cvt_tf32(float x) {
    uint32_t r;
    asm("cvt.rna.tf32.f32 %0, %1;" : "=r"(r) : "f"(x));
    return r;
}

// ---------------- tensor syrk: double-buffered stages, one sync/stage ----------------
// P = hh+hl, S = hl (+ folded loss reduction of prev iter)
__global__ __launch_bounds__(512) void k_syrk_mma(float* __restrict__ out, int prev_iter) {
    extern __shared__ uint32_t dsm[];   // 2 * BUFW words
    int tid = threadIdx.x, lane = tid & 31, w = tid >> 5;
    int gid = lane >> 2, tig = lane & 3;
    int ks = blockIdx.x, b = blockIdx.y;

    if (prev_iter >= 0 && ks == 0 && b == 0 && w == 0) {
        double s0 = 0.0, s1 = 0.0;
        for (int j = lane; j < 128; j += 32) {
            s0 += (double)d_loss[j * 2];
            s1 += (double)d_loss[j * 2 + 1];
        }
#pragma unroll
        for (int off = 16; off >= 1; off >>= 1) {
            s0 += __shfl_down_sync(0xffffffffu, s0, off);
            s1 += __shfl_down_sync(0xffffffffu, s1, off);
        }
        if (lane == 0) {
            out[TOTN + prev_iter] = (float)(s1 / (double)TOTN);
            out[TOTN + 10 + prev_iter] = (float)(s0 / (double)TOTN);
        }
    }

    const float* Lb = d_L + (size_t)b * CHA * NPIX + (size_t)ks * KC2;
    int wr = w >> 2, wc = w & 3;   // warp tile: rows 32*wr, cols 32*wc
    int f0 = tid * 2;

    float accH[8][4], accS[8][4];
#pragma unroll
    for (int i = 0; i < 8; i++)
#pragma unroll
        for (int j = 0; j < 4; j++) { accH[i][j] = 0.f; accS[i][j] = 0.f; }

    float4 pf[2];
    // prologue: stage 0 -> buf0
#pragma unroll
    for (int i = 0; i < 2; i++) {
        int f = f0 + i, row = f >> 3, c4 = f & 7;
        pf[i] = *(const float4*)&Lb[(size_t)row * NPIX + c4 * 4];
    }
    {
        uint32_t* Hs0 = dsm;
        uint32_t* Lo0 = dsm + 128 * SST;
#pragma unroll
        for (int i = 0; i < 2; i++) {
            int f = f0 + i, row = f >> 3, c4 = f & 7;
            int base = row * SST + c4 * 4;
            float v[4] = {pf[i].x, pf[i].y, pf[i].z, pf[i].w};
#pragma unroll
            for (int j = 0; j < 4; j++) {
                uint32_t h = cvt_tf32(v[j]);
                Hs0[base + j] = h;
                Lo0[base + j] = cvt_tf32(v[j] - __uint_as_float(h));
            }
        }
    }
    __syncthreads();
    // pf <- stage 1
#pragma unroll
    for (int i = 0; i < 2; i++) {
        int f = f0 + i, row = f >> 3, c4 = f & 7;
        pf[i] = *(const float4*)&Lb[(size_t)row * NPIX + 32 + c4 * 4];
    }

    for (int s = 0; s < 32; s++) {
        int p = s & 1;
        uint32_t* HsC = dsm + p * BUFW;
        uint32_t* LoC = HsC + 128 * SST;
        // 1) convert stage s+1 (in pf) into the other buffer
        if (s < 31) {
            uint32_t* HsN = dsm + (p ^ 1) * BUFW;
            uint32_t* LoN = HsN + 128 * SST;
#pragma unroll
            for (int i = 0; i < 2; i++) {
                int f = f0 + i, row = f >> 3, c4 = f & 7;
                int base = row * SST + c4 * 4;
                float v[4] = {pf[i].x, pf[i].y, pf[i].z, pf[i].w};
#pragma unroll
                for (int j = 0; j < 4; j++) {
                    uint32_t h = cvt_tf32(v[j]);
                    HsN[base + j] = h;
                    LoN[base + j] = cvt_tf32(v[j] - __uint_as_float(h));
                }
            }
        }
        // 2) prefetch stage s+2
        if (s < 30) {
#pragma unroll
            for (int i = 0; i < 2; i++) {
                int f = f0 + i, row = f >> 3, c4 = f & 7;
                pf[i] = *(const float4*)&Lb[(size_t)row * NPIX + (s + 2) * 32 + c4 * 4];
            }
        }
        // 3) MMAs on current buffer
#pragma unroll
        for (int kst = 0; kst < 4; kst++) {
            int k0 = kst * 8;
            uint32_t ah[2][4];
#pragma unroll
            for (int h = 0; h < 2; h++) {
                int m = wr * 32 + h * 16;
                ah[h][0] = HsC[(m + gid) * SST + k0 + tig];
                ah[h][1] = HsC[(m + gid + 8) * SST + k0 + tig];
                ah[h][2] = HsC[(m + gid) * SST + k0 + tig + 4];
                ah[h][3] = HsC[(m + gid + 8) * SST + k0 + tig + 4];
            }
#pragma unroll
            for (int nt = 0; nt < 4; nt++) {
                int n = wc * 32 + nt * 8 + gid;
                uint32_t bh0 = HsC[n * SST + k0 + tig];
                uint32_t bh1 = HsC[n * SST + k0 + tig + 4];
                uint32_t bl0 = LoC[n * SST + k0 + tig];
                uint32_t bl1 = LoC[n * SST + k0 + tig + 4];
#pragma unroll
                for (int h = 0; h < 2; h++) {
                    mma8(accH[h * 4 + nt], ah[h], bh0, bh1);
                    mma8(accS[h * 4 + nt], ah[h], bl0, bl1);
                }
            }
        }
        __syncthreads();
    }

    float* Gp = d_Gp + ((size_t)ks * BANDS + b) * CHA * CHA;
    float* Gs = d_Gs + ((size_t)ks * BANDS + b) * CHA * CHA;
#pragma unroll
    for (int h = 0; h < 2; h++) {
        int m = wr * 32 + h * 16;
#pragma unroll
        for (int nt = 0; nt < 4; nt++) {
            int n = wc * 32 + nt * 8 + 2 * tig;
            int t = h * 4 + nt;
            *(float2*)&Gp[(size_t)(m + gid) * 128 + n] =
                make_float2(accH[t][0] + accS[t][0], accH[t][1] + accS[t][1]);
            *(float2*)&Gp[(size_t)(m + gid + 8) * 128 + n] =
                make_float2(accH[t][2] + accS[t][2], accH[t][3] + accS[t][3]);
            *(float2*)&Gs[(size_t)(m + gid) * 128 + n] = make_float2(accS[t][0], accS[t][1]);
            *(float2*)&Gs[(size_t)(m + gid + 8) * 128 + n] = make_float2(accS[t][2], accS[t][3]);
        }
    }
}

// ---------------- G = sum_ks (P + S^T) ----------------
__global__ void k_gsum() {
    unsigned idx = blockIdx.x * 2048u + threadIdx.x;
    for (unsigned e = idx; e < idx + 2048u; e += 256u) {
        unsigned bb = e >> 14, i = (e >> 7) & 127u, j = e & 127u;
        float s = 0.f;
#pragma unroll
        for (int ks = 0; ks < KSP; ks++) {
            size_t base = ((size_t)ks * BANDS + bb) * CHA * CHA;
            s += d_Gp[base + i * 128 + j];
            s += d_Gs[base + j * 128 + i];
        }
        d_G[e] = s;
    }
}

// ---------------- eig helpers ----------------
#define AS 132
#define YS 20
#define CS 18

__device__ void matY(float* dst, const float* A, int st, const float* Ys, int tid) {
    int i0 = (tid & 31) * 4, j0 = (tid >> 5) * 2;
    float acc[4][2] = {{0,0},{0,0},{0,0},{0,0}};
#pragma unroll 4
    for (int k = 0; k < 128; k++) {
        float4 a = *(const float4*)&A[k * st + i0];
        float2 y = *(const float2*)&Ys[k * YS + j0];
        float av[4] = {a.x,a.y,a.z,a.w};
#pragma unroll
        for (int ii = 0; ii < 4; ii++) { acc[ii][0] += av[ii] * y.x; acc[ii][1] += av[ii] * y.y; }
    }
#pragma unroll
    for (int ii = 0; ii < 4; ii++) {
        dst[(i0 + ii) * YS + j0] = acc[ii][0];
        dst[(i0 + ii) * YS + j0 + 1] = acc[ii][1];
    }
    __syncthreads();
}

__device__ void qrP(float* Yb, float* red, int tid, int passes) {
    for (int j = 0; j < 16; j++) {
        for (int pass = 0; pass < passes; pass++) {
            if (j > 0) {
                int i = tid >> 4, kc = tid & 15;
                float pp = 0.f;
                if (i < j) {
#pragma unroll
                    for (int kk = 0; kk < 8; kk++) {
                        int k = kc * 8 + kk;
                        pp += Yb[k * YS + i] * Yb[k * YS + j];
                    }
                }
                red[i * 16 + kc] = pp;
                __syncthreads();
                if (tid < 16) {
                    float s = 0.f;
#pragma unroll
                    for (int q = 0; q < 16; q++) s += red[tid * 16 + q];
                    red[256 + tid] = s;
                }
                __syncthreads();
                if (tid < 128) {
                    float v = Yb[tid * YS + j];
                    for (int i2 = 0; i2 < j; i2++) v -= red[256 + i2] * Yb[tid * YS + i2];
                    Yb[tid * YS + j] = v;
                }
                __syncthreads();
            }
        }
        float v = (tid < 128) ? Yb[tid * YS + j] : 0.f;
        red[tid] = v * v;
        __syncthreads();
        if (tid < 64) red[tid] += red[tid + 64] + red[tid + 128] + red[tid + 192];
        __syncthreads();
        if (tid < 32) {
            float s = red[tid] + red[tid + 32];
#pragma unroll
            for (int off = 16; off >= 1; off >>= 1) s += __shfl_down_sync(0xffffffffu, s, off);
            if (tid == 0) red[0] = s;
        }
        __syncthreads();
        float inv = rsqrtf(fmaxf(red[0], 1e-36f));
        if (tid < 128) Yb[tid * YS + j] = v * inv;
        __syncthreads();
    }
}

__device__ void jacobi16(float* Bm, float* Vm, int* pr, float* cs, int tid) {
    if (tid < 16)
        for (int q = 0; q < 16; q++) Vm[tid * CS + q] = (tid == q) ? 1.f : 0.f;
    __syncthreads();
    for (int sweep = 0; sweep < 5; sweep++) {
        for (int r = 0; r < 15; r++) {
            if (tid < 8) {
                int m = tid;
                int p = (m == 0) ? 0 : 1 + ((m - 1 + r) % 15);
                int q = 1 + ((14 - m + r) % 15);
                if (p > q) { int tmp = p; p = q; q = tmp; }
                float app = Bm[p * CS + p], aqq = Bm[q * CS + q], apq = Bm[p * CS + q];
                float c = 1.f, s = 0.f;
                if (fabsf(apq) > 1e-30f) {
                    float tau = (aqq - app) / (2.f * apq);
                    float tt = ((tau >= 0.f) ? 1.f : -1.f) / (fabsf(tau) + sqrtf(1.f + tau * tau));
                    c = rsqrtf(1.f + tt * tt);
                    s = tt * c;
                }
                pr[m * 2] = p; pr[m * 2 + 1] = q;
                cs[m * 2] = c; cs[m * 2 + 1] = s;
            }
            __syncthreads();
            if (tid < 128) {
                int m = tid >> 4, k = tid & 15;
                int p = pr[m * 2], q = pr[m * 2 + 1];
                float c = cs[m * 2], s = cs[m * 2 + 1];
                float bp = Bm[p * CS + k], bq = Bm[q * CS + k];
                Bm[p * CS + k] = c * bp - s * bq;
                Bm[q * CS + k] = s * bp + c * bq;
            }
            __syncthreads();
            if (tid < 128) {
                int m = tid >> 4, k = tid & 15;
                int p = pr[m * 2], q = pr[m * 2 + 1];
                float c = cs[m * 2], s = cs[m * 2 + 1];
                float bp = Bm[k * CS + p], bq = Bm[k * CS + q];
                Bm[k * CS + p] = c * bp - s * bq;
                Bm[k * CS + q] = s * bp + c * bq;
                float vp = Vm[k * CS + p], vq = Vm[k * CS + q];
                Vm[k * CS + p] = c * vp - s * vq;
                Vm[k * CS + q] = s * vp + c * vq;
            }
            __syncthreads();
        }
    }
}

// ---------------- per-band: MMA squaring chain (G^32) + subspace + RR ----------------
__global__ __launch_bounds__(256) void k_eig(int iter) {
    extern __shared__ float sm[];
    float* A   = sm;
    float* Y   = A + 128 * AS;
    float* Y2  = Y + 128 * YS;
    float* C   = Y2 + 128 * YS;
    float* V   = C + 16 * CS;
    float* red = V + 16 * CS;
    float* cs  = red + 320;
    int*   pr  = (int*)(cs + 32);
    uint32_t* B1 = (uint32_t*)(pr + 32);
    uint32_t* B0 = (uint32_t*)A;
    int tid = threadIdx.x, b = blockIdx.x;
    int lane = tid & 31, w = tid >> 5;
    int gid = lane >> 2, tig = lane & 3;
    int wr = w >> 1, wc = w & 1;

    const float* Gb = d_G + (size_t)b * CHA * CHA;
    for (int e = tid; e < CHA * CHA; e += 256)
        B0[(e >> 7) * AS + (e & 127)] = cvt_tf32(Gb[e]);
    __syncthreads();

    uint32_t* src = B0;
    uint32_t* dst = B1;
    for (int sq = 0; sq < 5; sq++) {
        float acc[16][4];
#pragma unroll
        for (int i = 0; i < 16; i++)
#pragma unroll
            for (int j = 0; j < 4; j++) acc[i][j] = 0.f;
#pragma unroll 2
        for (int kst = 0; kst < 16; kst++) {
            int k0 = kst * 8;
            uint32_t a[2][4];
#pragma unroll
            for (int h = 0; h < 2; h++) {
                int m = wr * 32 + h * 16;
                a[h][0] = src[(m + gid) * AS + k0 + tig];
                a[h][1] = src[(m + gid + 8) * AS + k0 + tig];
                a[h][2] = src[(m + gid) * AS + k0 + tig + 4];
                a[h][3] = src[(m + gid + 8) * AS + k0 + tig + 4];
            }
#pragma unroll
            for (int nt = 0; nt < 8; nt++) {
                int n = wc * 64 + nt * 8 + gid;
                uint32_t b0 = src[n * AS + k0 + tig];
                uint32_t b1 = src[n * AS + k0 + tig + 4];
#pragma unroll
                for (int h = 0; h < 2; h++) mma8(acc[h * 8 + nt], a[h], b0, b1);
            }
        }
        float dm = 0.f;
#pragma unroll
        for (int h = 0; h < 2; h++)
#pragma unroll
            for (int nt = 0; nt < 8; nt++) {
                int R = wr * 32 + h * 16 + gid, Ncol = wc * 64 + nt * 8 + 2 * tig;
                int t = h * 8 + nt;
                if (R == Ncol) dm = fmaxf(dm, fabsf(acc[t][0]));
                if (R == Ncol + 1) dm = fmaxf(dm, fabsf(acc[t][1]));
                if (R + 8 == Ncol) dm = fmaxf(dm, fabsf(acc[t][2]));
                if (R + 8 == Ncol + 1) dm = fmaxf(dm, fabsf(acc[t][3]));
            }
#pragma unroll
        for (int off = 16; off >= 1; off >>= 1) dm = fmaxf(dm, __shfl_xor_sync(0xffffffffu, dm, off));
        if (lane == 0) red[w] = dm;
        __syncthreads();
        float d = 1e-30f;
#pragma unroll
        for (int q = 0; q < 8; q++) d = fmaxf(d, red[q]);
        float inv = 1.0f / d;
#pragma unroll
        for (int h = 0; h < 2; h++)
#pragma unroll
            for (int nt = 0; nt < 8; nt++) {
                int R = wr * 32 + h * 16 + gid, Ncol = wc * 64 + nt * 8 + 2 * tig;
                int t = h * 8 + nt;
                dst[R * AS + Ncol] = cvt_tf32(acc[t][0] * inv);
                dst[R * AS + Ncol + 1] = cvt_tf32(acc[t][1] * inv);
                dst[(R + 8) * AS + Ncol] = cvt_tf32(acc[t][2] * inv);
                dst[(R + 8) * AS + Ncol + 1] = cvt_tf32(acc[t][3] * inv);
            }
        __syncthreads();
        uint32_t* tmp = src; src = dst; dst = tmp;
    }
    const float* F = (const float*)src;

    if (iter == 0) {
        for (int e = tid; e < 128 * 16; e += 256) {
            int k = e >> 4, j = e & 15;
            Y[k * YS + j] = hashf((uint32_t)((b * 131) * 2048 + e) * 2654435761u + 12345u);
        }
        __syncthreads();
        matY(Y2, F, AS, Y, tid);  qrP(Y2, red, tid, 1);
        matY(Y, F, AS, Y2, tid);  qrP(Y, red, tid, 1);
        matY(Y2, F, AS, Y, tid);  qrP(Y2, red, tid, 2);
    } else {
        const float* Yw = d_Yw + (size_t)b * 128 * 16;
        for (int e = tid; e < 128 * 16; e += 256) {
            int k = e >> 4, j = e & 15;
            Y[k * YS + j] = Yw[e];
        }
        __syncthreads();
        matY(Y2, F, AS, Y, tid);  qrP(Y2, red, tid, 2);
    }

    {
        float* Yw = d_Yw + (size_t)b * 128 * 16;
        for (int e = tid; e < 128 * 16; e += 256) {
            int k = e >> 4, j = e & 15;
            Yw[e] = Y2[k * YS + j];
        }
    }

    for (int e = tid; e < CHA * CHA; e += 256)
        A[(e >> 7) * AS + (e & 127)] = Gb[e];
    __syncthreads();
    matY(Y, A, AS, Y2, tid);

    {
        int a = tid & 15, bb = tid >> 4;
        float s = 0.f;
        for (int k = 0; k < 128; k++) s += Y2[k * YS + a] * Y[k * YS + bb];
        C[a * CS + bb] = s;
    }
    __syncthreads();

    jacobi16(C, V, pr, cs, tid);

    if (tid == 0) {
        int sel[3] = {-1, -1, -1};
        for (int r = 0; r < 3; r++) {
            float best = -1e30f; int bi = 0;
            for (int j = 0; j < 16; j++) {
                bool used = (j == sel[0]) || (j == sel[1]) || (j == sel[2]);
                float ev = C[j * CS + j];
                if (!used && ev > best) { best = ev; bi = j; }
            }
            sel[r] = bi; pr[r] = bi;
        }
    }
    __syncthreads();

    if (tid < 128) {
        for (int r = 0; r < 3; r++) {
            int j = pr[r];
            float u = 0.f;
#pragma unroll
            for (int q = 0; q < 16; q++) u += Y2[tid * YS + q] * V[q * CS + j];
            d_U[(size_t)b * 384 + tid * 3 + r] = u;
        }
    }
}

// ---------------- fused UtL + update L + losses + final UV (float4) ----------------
__global__ __launch_bounds__(256) void k_update(const float* __restrict__ x, const float* __restrict__ W,
                                                const float* __restrict__ xg, float* __restrict__ out,
                                                int iter, int wout) {
    __shared__ float sU[384];
    __shared__ float sr[256];
    int b = blockIdx.y, tid = threadIdx.x;
    int n = (blockIdx.x * 256 + tid) * 4;
    if (tid < 128) {
        sU[tid * 3]     = d_U[(size_t)b * 384 + tid * 3];
        sU[tid * 3 + 1] = d_U[(size_t)b * 384 + tid * 3 + 1];
        sU[tid * 3 + 2] = d_U[(size_t)b * 384 + tid * 3 + 2];
    }
    __syncthreads();

    const float* Lb = d_L + (size_t)b * CHA * NPIX;
    float4 t0 = {0,0,0,0}, t1 = {0,0,0,0}, t2 = {0,0,0,0};
#pragma unroll 4
    for (int c = 0; c < 128; c++) {
        float4 v = *(const float4*)&Lb[(size_t)c * NPIX + n];
        float u0 = sU[c * 3], u1 = sU[c * 3 + 1], u2 = sU[c * 3 + 2];
        t0.x += u0 * v.x; t0.y += u0 * v.y; t0.z += u0 * v.z; t0.w += u0 * v.w;
        t1.x += u1 * v.x; t1.y += u1 * v.y; t1.z += u1 * v.z; t1.w += u1 * v.w;
        t2.x += u2 * v.x; t2.y += u2 * v.y; t2.z += u2 * v.z; t2.w += u2 * v.w;
    }

    float rho = d_rho0 * powf(1.05f, (float)iter);
    float ls = 0.f, lf = 0.f;
    for (int c = 0; c < 128; c++) {
        size_t idx = ((size_t)b * 128 + c) * NPIX + n;
        float u0 = sU[c * 3], u1 = sU[c * 3 + 1], u2 = sU[c * 3 + 2];
        float4 xv = *(const float4*)&x[idx];
        float4 wv = *(const float4*)&W[idx];
        float4 gv = *(const float4*)&xg[idx];
        float4 uv;
        uv.x = u0 * t0.x + u1 * t1.x + u2 * t2.x;
        uv.y = u0 * t0.y + u1 * t1.y + u2 * t2.y;
        uv.z = u0 * t0.z + u1 * t1.z + u2 * t2.z;
        uv.w = u0 * t0.w + u1 * t1.w + u2 * t2.w;
        float4 Lnew;
        {
            float d0 = uv.x - gv.x, d1 = uv.y - gv.y, d2 = uv.z - gv.z, d3 = uv.w - gv.w;
            ls += d0*d0 + d1*d1 + d2*d2 + d3*d3;
            float e0 = uv.x - xv.x, e1 = uv.y - xv.y, e2 = uv.z - xv.z, e3 = uv.w - xv.w;
            lf += wv.x*e0*e0 + wv.y*e1*e1 + wv.z*e2*e2 + wv.w*e3*e3;
            float m0 = rho / (wv.x + rho), m1 = rho / (wv.y + rho);
            float m2 = rho / (wv.z + rho), m3 = rho / (wv.w + rho);
            Lnew.x = (1.f - m0) * xv.x + m0 * uv.x;
            Lnew.y = (1.f - m1) * xv.y + m1 * uv.y;
            Lnew.z = (1.f - m2) * xv.z + m2 * uv.z;
            Lnew.w = (1.f - m3) * xv.w + m3 * uv.w;
        }
        *(float4*)&d_L[idx] = Lnew;
        if (wout) *(float4*)&out[idx] = uv;
    }
    sr[tid] = ls; __syncthreads();
    for (int o = 128; o >= 1; o >>= 1) { if (tid < o) sr[tid] += sr[tid + o]; __syncthreads(); }
    if (tid == 0) d_loss[(blockIdx.y * 4 + blockIdx.x) * 2] = sr[0];
    __syncthreads();
    sr[tid] = lf; __syncthreads();
    for (int o = 128; o >= 1; o >>= 1) { if (tid < o) sr[tid] += sr[tid + o]; __syncthreads(); }
    if (tid == 0) d_loss[(blockIdx.y * 4 + blockIdx.x) * 2 + 1] = sr[0];
}

__global__ void k_lossred(float* out, int iter) {
    __shared__ double sd[512];
    int t = threadIdx.x;
    double s0 = 0.0, s1 = 0.0;
    for (int j = t; j < 128; j += 256) { s0 += (double)d_loss[j * 2]; s1 += (double)d_loss[j * 2 + 1]; }
    sd[t] = s0; sd[256 + t] = s1; __syncthreads();
    for (int o = 128; o >= 1; o >>= 1) {
        if (t < o) { sd[t] += sd[t + o]; sd[256 + t] += sd[256 + t + o]; }
        __syncthreads();
    }
    if (t == 0) {
        out[TOTN + iter] = (float)(sd[256] / (double)TOTN);
        out[TOTN + 10 + iter] = (float)(sd[0] / (double)TOTN);
    }
}

// ---------------- launch ----------------
extern "C" void kernel_launch(void* const* d_in, const int* in_sizes, int n_in,
                              void* d_out, int out_size) {
    const float* x = (const float*)d_in[0];
    const float* W = (const float*)d_in[1];
    const float* xg = (const float*)d_in[2];
    float* out = (float*)d_out;

    size_t eigsm = (size_t)(2 * 128 * AS + 2 * 128 * YS + 2 * 16 * CS + 320 + 32 + 32) * 4;
    size_t syrksm = (size_t)2 * BUFW * 4;   // 73728 bytes
    cudaFuncSetAttribute(k_eig, cudaFuncAttributeMaxDynamicSharedMemorySize, 164 * 1024);
    cudaFuncSetAttribute(k_syrk_mma, cudaFuncAttributeMaxDynamicSharedMemorySize, 96 * 1024);

    k_copy<<<1024, 256>>>(x);
    k_wsum<<<1024, 256>>>(W);
    k_rho<<<1, 256>>>();

    for (int i = 0; i < ITE; i++) {
        k_syrk_mma<<<dim3(KSP, BANDS), 512, syrksm>>>(out, i - 1);
        k_gsum<<<256, 256>>>();
        k_eig<<<BANDS, 256, eigsm>>>(i);
        k_update<<<dim3(4, BANDS), 256>>>(x, W, xg, out, i, (i == ITE - 1) ? 1 : 0);
    }
    k_lossred<<<1, 256>>>(out, ITE - 1);
}

// round 16
// speedup vs baseline: 1.0876x; 1.0368x over previous
#include <cuda_runtime.h>
#include <cstdint>
#include <math.h>

#define BANDS 32
#define CHA 128
#define NPIX 4096
#define TOTN 16777216u
#define KSP 4
#define KC2 1024
#define ITE 10
#define SST 36
#define BUFW (2 * 128 * SST)   // one stage buffer: Hs + Lo (uint32 words)

// ---------------- device scratch ----------------
__device__ float d_L[16777216];
__device__ float d_Gp[KSP * BANDS * CHA * CHA];   // per-ks full contribution P + S^T
__device__ float d_G[BANDS * CHA * CHA];
__device__ float d_U[BANDS * CHA * 3];
__device__ float d_Yw[BANDS * CHA * 16];
__device__ float d_red[1024];
__device__ float d_loss[512 * 2];
__device__ float d_rho0;

__device__ __forceinline__ float hashf(uint32_t h) {
    h ^= h >> 16; h *= 0x7feb352du; h ^= h >> 15; h *= 0x846ca68bu; h ^= h >> 16;
    return (float)(h & 0xffffffu) * (1.0f / 16777216.0f) - 0.5f;
}

// ---------------- L = x ----------------
__global__ void k_copy(const float* __restrict__ x) {
    unsigned i = blockIdx.x * blockDim.x + threadIdx.x;
    unsigned st = gridDim.x * blockDim.x;
    const float4* x4 = (const float4*)x;
    float4* L4 = (float4*)d_L;
    for (unsigned j = i; j < TOTN / 4; j += st) L4[j] = x4[j];
}

// ---------------- rho0 ----------------
__global__ void k_wsum(const float* __restrict__ W) {
    __shared__ float sr[256];
    float s = 0.f;
    unsigned st = gridDim.x * blockDim.x;
    for (unsigned i = blockIdx.x * blockDim.x + threadIdx.x; i < TOTN; i += st) s += W[i];
    sr[threadIdx.x] = s; __syncthreads();
    for (int o = 128; o >= 1; o >>= 1) { if ((int)threadIdx.x < o) sr[threadIdx.x] += sr[threadIdx.x + o]; __syncthreads(); }
    if (threadIdx.x == 0) d_red[blockIdx.x] = sr[0];
}
__global__ void k_rho() {
    __shared__ double sd[256];
    int t = threadIdx.x;
    double s = 0.0;
    for (int j = t; j < 1024; j += 256) s += (double)d_red[j];
    sd[t] = s; __syncthreads();
    for (int o = 128; o >= 1; o >>= 1) { if (t < o) sd[t] += sd[t + o]; __syncthreads(); }
    if (t == 0) d_rho0 = (float)(0.5 * sd[0] / (double)TOTN);
}

// ---------------- mma.sync tf32 helpers ----------------
__device__ __forceinline__ void mma8(float* c, const uint32_t* a, uint32_t b0, uint32_t b1) {
    asm volatile(
        "mma.sync.aligned.m16n8k8.row.col.f32.tf32.tf32.f32 "
        "{%0,%1,%2,%3}, {%4,%5,%6,%7}, {%8,%9}, {%0,%1,%2,%3};"
        : "+f"(c[0]), "+f"(c[1]), "+f"(c[2]), "+f"(c[3])
        : "r"(a[0]), "r"(a[1]), "r"(a[2]), "r"(a[3]), "r"(b0), "r"(b1));
}
__device__ __forceinline__ uint32_t cvt_tf32(float x) {
    uint32_t r;
    asm("cvt.rna.tf32.f32 %0, %1;" : "=r"(r) : "f"(x));
    return r;
}

// ---------------- tensor syrk: double-buffered stages + in-CTA symmetrization ----------------
// Gp[ks][b] = hh + hl + (hl)^T  (full per-ks contribution)
__global__ __launch_bounds__(512) void k_syrk_mma(float* __restrict__ out, int prev_iter) {
    extern __shared__ uint32_t dsm[];   // max(2*BUFW, 128*129) words
    int tid = threadIdx.x, lane = tid & 31, w = tid >> 5;
    int gid = lane >> 2, tig = lane & 3;
    int ks = blockIdx.x, b = blockIdx.y;

    if (prev_iter >= 0 && ks == 0 && b == 0 && w == 0) {
        double s0 = 0.0, s1 = 0.0;
        for (int j = lane; j < 128; j += 32) {
            s0 += (double)d_loss[j * 2];
            s1 += (double)d_loss[j * 2 + 1];
        }
#pragma unroll
        for (int off = 16; off >= 1; off >>= 1) {
            s0 += __shfl_down_sync(0xffffffffu, s0, off);
            s1 += __shfl_down_sync(0xffffffffu, s1, off);
        }
        if (lane == 0) {
            out[TOTN + prev_iter] = (float)(s1 / (double)TOTN);
            out[TOTN + 10 + prev_iter] = (float)(s0 / (double)TOTN);
        }
    }

    const float* Lb = d_L + (size_t)b * CHA * NPIX + (size_t)ks * KC2;
    int wr = w >> 2, wc = w & 3;   // warp tile: rows 32*wr, cols 32*wc
    int f0 = tid * 2;

    float accH[8][4], accS[8][4];
#pragma unroll
    for (int i = 0; i < 8; i++)
#pragma unroll
        for (int j = 0; j < 4; j++) { accH[i][j] = 0.f; accS[i][j] = 0.f; }

    float4 pf[2];
#pragma unroll
    for (int i = 0; i < 2; i++) {
        int f = f0 + i, row = f >> 3, c4 = f & 7;
        pf[i] = *(const float4*)&Lb[(size_t)row * NPIX + c4 * 4];
    }
    {
        uint32_t* Hs0 = dsm;
        uint32_t* Lo0 = dsm + 128 * SST;
#pragma unroll
        for (int i = 0; i < 2; i++) {
            int f = f0 + i, row = f >> 3, c4 = f & 7;
            int base = row * SST + c4 * 4;
            float v[4] = {pf[i].x, pf[i].y, pf[i].z, pf[i].w};
#pragma unroll
            for (int j = 0; j < 4; j++) {
                uint32_t h = cvt_tf32(v[j]);
                Hs0[base + j] = h;
                Lo0[base + j] = cvt_tf32(v[j] - __uint_as_float(h));
            }
        }
    }
    __syncthreads();
#pragma unroll
    for (int i = 0; i < 2; i++) {
        int f = f0 + i, row = f >> 3, c4 = f & 7;
        pf[i] = *(const float4*)&Lb[(size_t)row * NPIX + 32 + c4 * 4];
    }

    for (int s = 0; s < 32; s++) {
        int p = s & 1;
        uint32_t* HsC = dsm + p * BUFW;
        uint32_t* LoC = HsC + 128 * SST;
        if (s < 31) {
            uint32_t* HsN = dsm + (p ^ 1) * BUFW;
            uint32_t* LoN = HsN + 128 * SST;
#pragma unroll
            for (int i = 0; i < 2; i++) {
                int f = f0 + i, row = f >> 3, c4 = f & 7;
                int base = row * SST + c4 * 4;
                float v[4] = {pf[i].x, pf[i].y, pf[i].z, pf[i].w};
#pragma unroll
                for (int j = 0; j < 4; j++) {
                    uint32_t h = cvt_tf32(v[j]);
                    HsN[base + j] = h;
                    LoN[base + j] = cvt_tf32(v[j] - __uint_as_float(h));
                }
            }
        }
        if (s < 30) {
#pragma unroll
            for (int i = 0; i < 2; i++) {
                int f = f0 + i, row = f >> 3, c4 = f & 7;
                pf[i] = *(const float4*)&Lb[(size_t)row * NPIX + (s + 2) * 32 + c4 * 4];
            }
        }
#pragma unroll
        for (int kst = 0; kst < 4; kst++) {
            int k0 = kst * 8;
            uint32_t ah[2][4];
#pragma unroll
            for (int h = 0; h < 2; h++) {
                int m = wr * 32 + h * 16;
                ah[h][0] = HsC[(m + gid) * SST + k0 + tig];
                ah[h][1] = HsC[(m + gid + 8) * SST + k0 + tig];
                ah[h][2] = HsC[(m + gid) * SST + k0 + tig + 4];
                ah[h][3] = HsC[(m + gid + 8) * SST + k0 + tig + 4];
            }
#pragma unroll
            for (int nt = 0; nt < 4; nt++) {
                int n = wc * 32 + nt * 8 + gid;
                uint32_t bh0 = HsC[n * SST + k0 + tig];
                uint32_t bh1 = HsC[n * SST + k0 + tig + 4];
                uint32_t bl0 = LoC[n * SST + k0 + tig];
                uint32_t bl1 = LoC[n * SST + k0 + tig + 4];
#pragma unroll
                for (int h = 0; h < 2; h++) {
                    mma8(accH[h * 4 + nt], ah[h], bh0, bh1);
                    mma8(accS[h * 4 + nt], ah[h], bl0, bl1);
                }
            }
        }
        __syncthreads();
    }

    // ---- in-CTA symmetrization: stash S, read S^T, write Gp = H + S + S^T ----
    float* Ts = (float*)dsm;    // 128 x 129 floats (66048 B <= 73728 B dyn smem)
#pragma unroll
    for (int h = 0; h < 2; h++) {
        int m = wr * 32 + h * 16;
#pragma unroll
        for (int nt = 0; nt < 4; nt++) {
            int n = wc * 32 + nt * 8 + 2 * tig;
            int t = h * 4 + nt;
            Ts[(m + gid) * 129 + n]     = accS[t][0];
            Ts[(m + gid) * 129 + n + 1] = accS[t][1];
            Ts[(m + gid + 8) * 129 + n]     = accS[t][2];
            Ts[(m + gid + 8) * 129 + n + 1] = accS[t][3];
        }
    }
    __syncthreads();
    float* Gp = d_Gp + ((size_t)ks * BANDS + b) * CHA * CHA;
#pragma unroll
    for (int h = 0; h < 2; h++) {
        int m = wr * 32 + h * 16;
#pragma unroll
        for (int nt = 0; nt < 4; nt++) {
            int n = wc * 32 + nt * 8 + 2 * tig;
            int t = h * 4 + nt;
            float st00 = Ts[n * 129 + (m + gid)];
            float st01 = Ts[(n + 1) * 129 + (m + gid)];
            float st10 = Ts[n * 129 + (m + gid + 8)];
            float st11 = Ts[(n + 1) * 129 + (m + gid + 8)];
            *(float2*)&Gp[(size_t)(m + gid) * 128 + n] =
                make_float2(accH[t][0] + accS[t][0] + st00, accH[t][1] + accS[t][1] + st01);
            *(float2*)&Gp[(size_t)(m + gid + 8) * 128 + n] =
                make_float2(accH[t][2] + accS[t][2] + st10, accH[t][3] + accS[t][3] + st11);
        }
    }
}

// ---------------- G = sum_ks Gp (fully coalesced) ----------------
__global__ void k_gsum() {
    unsigned idx = blockIdx.x * 2048u + threadIdx.x;
    for (unsigned e = idx; e < idx + 2048u; e += 256u) {
        unsigned bb = e >> 14, el = e & 16383u;
        float s = 0.f;
#pragma unroll
        for (int ks = 0; ks < KSP; ks++)
            s += d_Gp[((size_t)ks * BANDS + bb) * CHA * CHA + el];
        d_G[e] = s;
    }
}

// ---------------- eig helpers ----------------
#define AS 132
#define YS 20
#define CS 18

__device__ void matY(float* dst, const float* A, int st, const float* Ys, int tid) {
    int i0 = (tid & 31) * 4, j0 = (tid >> 5) * 2;
    float acc[4][2] = {{0,0},{0,0},{0,0},{0,0}};
#pragma unroll 4
    for (int k = 0; k < 128; k++) {
        float4 a = *(const float4*)&A[k * st + i0];
        float2 y = *(const float2*)&Ys[k * YS + j0];
        float av[4] = {a.x,a.y,a.z,a.w};
#pragma unroll
        for (int ii = 0; ii < 4; ii++) { acc[ii][0] += av[ii] * y.x; acc[ii][1] += av[ii] * y.y; }
    }
#pragma unroll
    for (int ii = 0; ii < 4; ii++) {
        dst[(i0 + ii) * YS + j0] = acc[ii][0];
        dst[(i0 + ii) * YS + j0 + 1] = acc[ii][1];
    }
    __syncthreads();
}

__device__ void qrP(float* Yb, float* red, int tid, int passes) {
    for (int j = 0; j < 16; j++) {
        for (int pass = 0; pass < passes; pass++) {
            if (j > 0) {
                int i = tid >> 4, kc = tid & 15;
                float pp = 0.f;
                if (i < j) {
#pragma unroll
                    for (int kk = 0; kk < 8; kk++) {
                        int k = kc * 8 + kk;
                        pp += Yb[k * YS + i] * Yb[k * YS + j];
                    }
                }
                red[i * 16 + kc] = pp;
                __syncthreads();
                if (tid < 16) {
                    float s = 0.f;
#pragma unroll
                    for (int q = 0; q < 16; q++) s += red[tid * 16 + q];
                    red[256 + tid] = s;
                }
                __syncthreads();
                if (tid < 128) {
                    float v = Yb[tid * YS + j];
                    for (int i2 = 0; i2 < j; i2++) v -= red[256 + i2] * Yb[tid * YS + i2];
                    Yb[tid * YS + j] = v;
                }
                __syncthreads();
            }
        }
        float v = (tid < 128) ? Yb[tid * YS + j] : 0.f;
        red[tid] = v * v;
        __syncthreads();
        if (tid < 64) red[tid] += red[tid + 64] + red[tid + 128] + red[tid + 192];
        __syncthreads();
        if (tid < 32) {
            float s = red[tid] + red[tid + 32];
#pragma unroll
            for (int off = 16; off >= 1; off >>= 1) s += __shfl_down_sync(0xffffffffu, s, off);
            if (tid == 0) red[0] = s;
        }
        __syncthreads();
        float inv = rsqrtf(fmaxf(red[0], 1e-36f));
        if (tid < 128) Yb[tid * YS + j] = v * inv;
        __syncthreads();
    }
}

__device__ void jacobi16(float* Bm, float* Vm, int* pr, float* cs, int tid) {
    if (tid < 16)
        for (int q = 0; q < 16; q++) Vm[tid * CS + q] = (tid == q) ? 1.f : 0.f;
    __syncthreads();
    for (int sweep = 0; sweep < 5; sweep++) {
        for (int r = 0; r < 15; r++) {
            if (tid < 8) {
                int m = tid;
                int p = (m == 0) ? 0 : 1 + ((m - 1 + r) % 15);
                int q = 1 + ((14 - m + r) % 15);
                if (p > q) { int tmp = p; p = q; q = tmp; }
                float app = Bm[p * CS + p], aqq = Bm[q * CS + q], apq = Bm[p * CS + q];
                float c = 1.f, s = 0.f;
                if (fabsf(apq) > 1e-30f) {
                    float tau = (aqq - app) / (2.f * apq);
                    float tt = ((tau >= 0.f) ? 1.f : -1.f) / (fabsf(tau) + sqrtf(1.f + tau * tau));
                    c = rsqrtf(1.f + tt * tt);
                    s = tt * c;
                }
                pr[m * 2] = p; pr[m * 2 + 1] = q;
                cs[m * 2] = c; cs[m * 2 + 1] = s;
            }
            __syncthreads();
            if (tid < 128) {
                int m = tid >> 4, k = tid & 15;
                int p = pr[m * 2], q = pr[m * 2 + 1];
                float c = cs[m * 2], s = cs[m * 2 + 1];
                float bp = Bm[p * CS + k], bq = Bm[q * CS + k];
                Bm[p * CS + k] = c * bp - s * bq;
                Bm[q * CS + k] = s * bp + c * bq;
            }
            __syncthreads();
            if (tid < 128) {
                int m = tid >> 4, k = tid & 15;
                int p = pr[m * 2], q = pr[m * 2 + 1];
                float c = cs[m * 2], s = cs[m * 2 + 1];
                float bp = Bm[k * CS + p], bq = Bm[k * CS + q];
                Bm[k * CS + p] = c * bp - s * bq;
                Bm[k * CS + q] = s * bp + c * bq;
                float vp = Vm[k * CS + p], vq = Vm[k * CS + q];
                Vm[k * CS + p] = c * vp - s * vq;
                Vm[k * CS + q] = s * vp + c * vq;
            }
            __syncthreads();
        }
    }
}

// ---------------- per-band: MMA squaring chain (G^32) + subspace + RR ----------------
__global__ __launch_bounds__(256) void k_eig(int iter) {
    extern __shared__ float sm[];
    float* A   = sm;
    float* Y   = A + 128 * AS;
    float* Y2  = Y + 128 * YS;
    float* C   = Y2 + 128 * YS;
    float* V   = C + 16 * CS;
    float* red = V + 16 * CS;
    float* cs  = red + 320;
    int*   pr  = (int*)(cs + 32);
    uint32_t* B1 = (uint32_t*)(pr + 32);
    uint32_t* B0 = (uint32_t*)A;
    int tid = threadIdx.x, b = blockIdx.x;
    int lane = tid & 31, w = tid >> 5;
    int gid = lane >> 2, tig = lane & 3;
    int wr = w >> 1, wc = w & 1;

    const float* Gb = d_G + (size_t)b * CHA * CHA;
    for (int e = tid; e < CHA * CHA; e += 256)
        B0[(e >> 7) * AS + (e & 127)] = cvt_tf32(Gb[e]);
    __syncthreads();

    uint32_t* src = B0;
    uint32_t* dst = B1;
    for (int sq = 0; sq < 5; sq++) {
        float acc[16][4];
#pragma unroll
        for (int i = 0; i < 16; i++)
#pragma unroll
            for (int j = 0; j < 4; j++) acc[i][j] = 0.f;
#pragma unroll 2
        for (int kst = 0; kst < 16; kst++) {
            int k0 = kst * 8;
            uint32_t a[2][4];
#pragma unroll
            for (int h = 0; h < 2; h++) {
                int m = wr * 32 + h * 16;
                a[h][0] = src[(m + gid) * AS + k0 + tig];
                a[h][1] = src[(m + gid + 8) * AS + k0 + tig];
                a[h][2] = src[(m + gid) * AS + k0 + tig + 4];
                a[h][3] = src[(m + gid + 8) * AS + k0 + tig + 4];
            }
#pragma unroll
            for (int nt = 0; nt < 8; nt++) {
                int n = wc * 64 + nt * 8 + gid;
                uint32_t b0 = src[n * AS + k0 + tig];
                uint32_t b1 = src[n * AS + k0 + tig + 4];
#pragma unroll
                for (int h = 0; h < 2; h++) mma8(acc[h * 8 + nt], a[h], b0, b1);
            }
        }
        float dm = 0.f;
#pragma unroll
        for (int h = 0; h < 2; h++)
#pragma unroll
            for (int nt = 0; nt < 8; nt++) {
                int R = wr * 32 + h * 16 + gid, Ncol = wc * 64 + nt * 8 + 2 * tig;
                int t = h * 8 + nt;
                if (R == Ncol) dm = fmaxf(dm, fabsf(acc[t][0]));
                if (R == Ncol + 1) dm = fmaxf(dm, fabsf(acc[t][1]));
                if (R + 8 == Ncol) dm = fmaxf(dm, fabsf(acc[t][2]));
                if (R + 8 == Ncol + 1) dm = fmaxf(dm, fabsf(acc[t][3]));
            }
#pragma unroll
        for (int off = 16; off >= 1; off >>= 1) dm = fmaxf(dm, __shfl_xor_sync(0xffffffffu, dm, off));
        if (lane == 0) red[w] = dm;
        __syncthreads();
        float d = 1e-30f;
#pragma unroll
        for (int q = 0; q < 8; q++) d = fmaxf(d, red[q]);
        float inv = 1.0f / d;
#pragma unroll
        for (int h = 0; h < 2; h++)
#pragma unroll
            for (int nt = 0; nt < 8; nt++) {
                int R = wr * 32 + h * 16 + gid, Ncol = wc * 64 + nt * 8 + 2 * tig;
                int t = h * 8 + nt;
                dst[R * AS + Ncol] = cvt_tf32(acc[t][0] * inv);
                dst[R * AS + Ncol + 1] = cvt_tf32(acc[t][1] * inv);
                dst[(R + 8) * AS + Ncol] = cvt_tf32(acc[t][2] * inv);
                dst[(R + 8) * AS + Ncol + 1] = cvt_tf32(acc[t][3] * inv);
            }
        __syncthreads();
        uint32_t* tmp = src; src = dst; dst = tmp;
    }
    const float* F = (const float*)src;

    if (iter == 0) {
        for (int e = tid; e < 128 * 16; e += 256) {
            int k = e >> 4, j = e & 15;
            Y[k * YS + j] = hashf((uint32_t)((b * 131) * 2048 + e) * 2654435761u + 12345u);
        }
        __syncthreads();
        matY(Y2, F, AS, Y, tid);  qrP(Y2, red, tid, 1);
        matY(Y, F, AS, Y2, tid);  qrP(Y, red, tid, 1);
        matY(Y2, F, AS, Y, tid);  qrP(Y2, red, tid, 2);
    } else {
        const float* Yw = d_Yw + (size_t)b * 128 * 16;
        for (int e = tid; e < 128 * 16; e += 256) {
            int k = e >> 4, j = e & 15;
            Y[k * YS + j] = Yw[e];
        }
        __syncthreads();
        matY(Y2, F, AS, Y, tid);  qrP(Y2, red, tid, 2);
    }

    {
        float* Yw = d_Yw + (size_t)b * 128 * 16;
        for (int e = tid; e < 128 * 16; e += 256) {
            int k = e >> 4, j = e & 15;
            Yw[e] = Y2[k * YS + j];
        }
    }

    for (int e = tid; e < CHA * CHA; e += 256)
        A[(e >> 7) * AS + (e & 127)] = Gb[e];
    __syncthreads();
    matY(Y, A, AS, Y2, tid);

    {
        int a = tid & 15, bb = tid >> 4;
        float s = 0.f;
        for (int k = 0; k < 128; k++) s += Y2[k * YS + a] * Y[k * YS + bb];
        C[a * CS + bb] = s;
    }
    __syncthreads();

    jacobi16(C, V, pr, cs, tid);

    if (tid == 0) {
        int sel[3] = {-1, -1, -1};
        for (int r = 0; r < 3; r++) {
            float best = -1e30f; int bi = 0;
            for (int j = 0; j < 16; j++) {
                bool used = (j == sel[0]) || (j == sel[1]) || (j == sel[2]);
                float ev = C[j * CS + j];
                if (!used && ev > best) { best = ev; bi = j; }
            }
            sel[r] = bi; pr[r] = bi;
        }
    }
    __syncthreads();

    if (tid < 128) {
        for (int r = 0; r < 3; r++) {
            int j = pr[r];
            float u = 0.f;
#pragma unroll
            for (int q = 0; q < 16; q++) u += Y2[tid * YS + q] * V[q * CS + j];
            d_U[(size_t)b * 384 + tid * 3 + r] = u;
        }
    }
}

// ---------------- fused UtL + update L + losses + final UV (float4) ----------------
__global__ __launch_bounds__(256) void k_update(const float* __restrict__ x, const float* __restrict__ W,
                                                const float* __restrict__ xg, float* __restrict__ out,
                                                int iter, int wout) {
    __shared__ float sU[384];
    __shared__ float sr[256];
    int b = blockIdx.y, tid = threadIdx.x;
    int n = (blockIdx.x * 256 + tid) * 4;
    if (tid < 128) {
        sU[tid * 3]     = d_U[(size_t)b * 384 + tid * 3];
        sU[tid * 3 + 1] = d_U[(size_t)b * 384 + tid * 3 + 1];
        sU[tid * 3 + 2] = d_U[(size_t)b * 384 + tid * 3 + 2];
    }
    __syncthreads();

    const float* Lb = d_L + (size_t)b * CHA * NPIX;
    float4 t0 = {0,0,0,0}, t1 = {0,0,0,0}, t2 = {0,0,0,0};
#pragma unroll 4
    for (int c = 0; c < 128; c++) {
        float4 v = *(const float4*)&Lb[(size_t)c * NPIX + n];
        float u0 = sU[c * 3], u1 = sU[c * 3 + 1], u2 = sU[c * 3 + 2];
        t0.x += u0 * v.x; t0.y += u0 * v.y; t0.z += u0 * v.z; t0.w += u0 * v.w;
        t1.x += u1 * v.x; t1.y += u1 * v.y; t1.z += u1 * v.z; t1.w += u1 * v.w;
        t2.x += u2 * v.x; t2.y += u2 * v.y; t2.z += u2 * v.z; t2.w += u2 * v.w;
    }

    float rho = d_rho0 * powf(1.05f, (float)iter);
    float ls = 0.f, lf = 0.f;
    for (int c = 0; c < 128; c++) {
        size_t idx = ((size_t)b * 128 + c) * NPIX + n;
        float u0 = sU[c * 3], u1 = sU[c * 3 + 1], u2 = sU[c * 3 + 2];
        float4 xv = *(const float4*)&x[idx];
        float4 wv = *(const float4*)&W[idx];
        float4 gv = *(const float4*)&xg[idx];
        float4 uv;
        uv.x = u0 * t0.x + u1 * t1.x + u2 * t2.x;
        uv.y = u0 * t0.y + u1 * t1.y + u2 * t2.y;
        uv.z = u0 * t0.z + u1 * t1.z + u2 * t2.z;
        uv.w = u0 * t0.w + u1 * t1.w + u2 * t2.w;
        float4 Lnew;
        {
            float d0 = uv.x - gv.x, d1 = uv.y - gv.y, d2 = uv.z - gv.z, d3 = uv.w - gv.w;
            ls += d0*d0 + d1*d1 + d2*d2 + d3*d3;
            float e0 = uv.x - xv.x, e1 = uv.y - xv.y, e2 = uv.z - xv.z, e3 = uv.w - xv.w;
            lf += wv.x*e0*e0 + wv.y*e1*e1 + wv.z*e2*e2 + wv.w*e3*e3;
            float m0 = rho / (wv.x + rho), m1 = rho / (wv.y + rho);
            float m2 = rho / (wv.z + rho), m3 = rho / (wv.w + rho);
            Lnew.x = (1.f - m0) * xv.x + m0 * uv.x;
            Lnew.y = (1.f - m1) * xv.y + m1 * uv.y;
            Lnew.z = (1.f - m2) * xv.z + m2 * uv.z;
            Lnew.w = (1.f - m3) * xv.w + m3 * uv.w;
        }
        *(float4*)&d_L[idx] = Lnew;
        if (wout) *(float4*)&out[idx] = uv;
    }
    sr[tid] = ls; __syncthreads();
    for (int o = 128; o >= 1; o >>= 1) { if (tid < o) sr[tid] += sr[tid + o]; __syncthreads(); }
    if (tid == 0) d_loss[(blockIdx.y * 4 + blockIdx.x) * 2] = sr[0];
    __syncthreads();
    sr[tid] = lf; __syncthreads();
    for (int o = 128; o >= 1; o >>= 1) { if (tid < o) sr[tid] += sr[tid + o]; __syncthreads(); }
    if (tid == 0) d_loss[(blockIdx.y * 4 + blockIdx.x) * 2 + 1] = sr[0];
}

__global__ void k_lossred(float* out, int iter) {
    __shared__ double sd[512];
    int t = threadIdx.x;
    double s0 = 0.0, s1 = 0.0;
    for (int j = t; j < 128; j += 256) { s0 += (double)d_loss[j * 2]; s1 += (double)d_loss[j * 2 + 1]; }
    sd[t] = s0; sd[256 + t] = s1; __syncthreads();
    for (int o = 128; o >= 1; o >>= 1) {
        if (t < o) { sd[t] += sd[t + o]; sd[256 + t] += sd[256 + t + o]; }
        __syncthreads();
    }
    if (t == 0) {
        out[TOTN + iter] = (float)(sd[256] / (double)TOTN);
        out[TOTN + 10 + iter] = (float)(sd[0] / (double)TOTN);
    }
}

// ---------------- launch ----------------
extern "C" void kernel_launch(void* const* d_in, const int* in_sizes, int n_in,
                              void* d_out, int out_size) {
    const float* x = (const float*)d_in[0];
    const float* W = (const float*)d_in[1];
    const float* xg = (const float*)d_in[2];
    float* out = (float*)d_out;

    size_t eigsm = (size_t)(2 * 128 * AS + 2 * 128 * YS + 2 * 16 * CS + 320 + 32 + 32) * 4;
    size_t syrksm = (size_t)2 * BUFW * 4;   // 73728 B (>= 128*129*4 = 66048 B)
    cudaFuncSetAttribute(k_eig, cudaFuncAttributeMaxDynamicSharedMemorySize, 164 * 1024);
    cudaFuncSetAttribute(k_syrk_mma, cudaFuncAttributeMaxDynamicSharedMemorySize, 96 * 1024);

    k_copy<<<1024, 256>>>(x);
    k_wsum<<<1024, 256>>>(W);
    k_rho<<<1, 256>>>();

    for (int i = 0; i < ITE; i++) {
        k_syrk_mma<<<dim3(KSP, BANDS), 512, syrksm>>>(out, i - 1);
        k_gsum<<<256, 256>>>();
        k_eig<<<BANDS, 256, eigsm>>>(i);
        k_update<<<dim3(4, BANDS), 256>>>(x, W, xg, out, i, (i == ITE - 1) ? 1 : 0);
    }
    k_lossred<<<1, 256>>>(out, ITE - 1);
}